// round 15
// baseline (speedup 1.0000x reference)
#include <cuda_runtime.h>
#include <cuda_bf16.h>
#include <cuda_fp16.h>
#include <math.h>
#include <stdint.h>

// ---------------------------------------------------------------------------
// GPT-2 small forward: L=6, C=768, H=12, D=64, B=4, T=1024, V=32000
// Output layout: logits [4096*32000] | loss [1] | x_final [4096*768]
// Round 15: warp-per-row LN (no block syncs), hgemm K-chunk 64 (half the
// barriers), float4 loss reads.  fp16 mma GEMMs + flash attention.
// ---------------------------------------------------------------------------

#define BT   4096
#define CH   768
#define NH   12
#define DH   64
#define TSEQ 1024
#define VOC  32000
#define NLAY 6

#define W_ATTN_OFF 0
#define W_ATTN_SZ  (2304 * 768)
#define W_PROJ_OFF (W_ATTN_OFF + 6 * W_ATTN_SZ)
#define W_PROJ_SZ  (768 * 768)
#define W_FC_OFF   (W_PROJ_OFF + 6 * W_PROJ_SZ)
#define W_FC_SZ    (3072 * 768)
#define W_FC2_OFF  (W_FC_OFF + 6 * W_FC_SZ)
#define W_FC2_SZ   (768 * 3072)
#define W_TOTAL    (W_FC2_OFF + 6 * W_FC2_SZ)

// Scratch (device globals: no allocation allowed)
__device__ float g_x[BT * CH];
__device__ float g_hf[BT * CH];
__device__ __half g_qkv_h[BT * 3 * CH];
__device__ __half g_h_h[BT * CH];
__device__ __half g_y_h[BT * CH];
__device__ __half g_m_h[BT * 4 * CH];
__device__ __half g_wt_h[W_TOTAL];
__device__ __half g_wte_h[VOC * CH];
__device__ float g_num;
__device__ float g_den;

// ---------------------------------------------------------------------------
__global__ void conv_k(const float4* __restrict__ src, __half* __restrict__ dst, int n4) {
    int i = blockIdx.x * 256 + threadIdx.x;
    if (i < n4) {
        float4 v = src[i];
        *(__half2*)&dst[i * 4] = __floats2half2_rn(v.x, v.y);
        *(__half2*)&dst[i * 4 + 2] = __floats2half2_rn(v.z, v.w);
    }
}

// batched transpose + convert: W[l][K,N] fp32 -> T[l][N,K] fp16, blockIdx.z = layer
__global__ void tconv_k(const float* __restrict__ W, __half* __restrict__ T,
                        int K, int N, size_t wstride, size_t tstride) {
    __shared__ float s[32][33];
    int n0 = blockIdx.x * 32, k0 = blockIdx.y * 32;
    const float* Wl = W + (size_t)blockIdx.z * wstride;
    __half* Tl = T + (size_t)blockIdx.z * tstride;
    int tx = threadIdx.x, ty = threadIdx.y;
#pragma unroll
    for (int i = 0; i < 4; i++)
        s[ty + i * 8][tx] = Wl[(size_t)(k0 + ty + i * 8) * N + n0 + tx];
    __syncthreads();
#pragma unroll
    for (int i = 0; i < 4; i++)
        Tl[(size_t)(n0 + ty + i * 8) * K + k0 + tx] = __float2half(s[tx][ty + i * 8]);
}

// ---------------------------------------------------------------------------
__global__ void embed_k(const int* __restrict__ idx, const float* __restrict__ wte,
                        const float* __restrict__ wpe, float* __restrict__ x) {
    int row = blockIdx.x;
    int t = row & (TSEQ - 1);
    int tok = idx[row];
    const float* a = wte + (size_t)tok * CH;
    const float* b = wpe + (size_t)t * CH;
    float* o = x + (size_t)row * CH;
    for (int c = threadIdx.x; c < CH; c += blockDim.x) o[c] = a[c] + b[c];
}

__global__ void copy_k(const float* __restrict__ src, float* __restrict__ dst, int n) {
    int i = blockIdx.x * blockDim.x + threadIdx.x;
    if (i < n) dst[i] = src[i];
}

// LayerNorm: one WARP per row, float4 loads, shfl reductions, no block sync.
// WF32: also write fp32 output (final LN only).  Grid: BT/8 blocks x 256 thr.
template <int WF32>
__global__ void ln_k(const float* __restrict__ x, const float* __restrict__ g,
                     const float* __restrict__ b, float* __restrict__ o,
                     __half* __restrict__ oh) {
    int row = blockIdx.x * 8 + (threadIdx.x >> 5);
    int lane = threadIdx.x & 31;
    const float4* xr = (const float4*)(x + (size_t)row * CH);
    float4 v[6];
    float s = 0.f, s2 = 0.f;
#pragma unroll
    for (int i = 0; i < 6; i++) {
        v[i] = xr[lane + i * 32];
        s  += v[i].x + v[i].y + v[i].z + v[i].w;
        s2 += v[i].x * v[i].x + v[i].y * v[i].y + v[i].z * v[i].z + v[i].w * v[i].w;
    }
#pragma unroll
    for (int off = 16; off > 0; off >>= 1) {
        s  += __shfl_xor_sync(0xffffffffu, s, off);
        s2 += __shfl_xor_sync(0xffffffffu, s2, off);
    }
    float mean = s * (1.0f / CH);
    float var  = s2 * (1.0f / CH) - mean * mean;
    float rstd = rsqrtf(var + 1e-5f);
    const float4* gg = (const float4*)g;
    const float4* bb = (const float4*)b;
#pragma unroll
    for (int i = 0; i < 6; i++) {
        int c4 = lane + i * 32;
        float4 gv = gg[c4], bv = bb[c4];
        float o0 = (v[i].x - mean) * rstd * gv.x + bv.x;
        float o1 = (v[i].y - mean) * rstd * gv.y + bv.y;
        float o2 = (v[i].z - mean) * rstd * gv.z + bv.z;
        float o3 = (v[i].w - mean) * rstd * gv.w + bv.w;
        size_t oo = (size_t)row * CH + c4 * 4;
        if (WF32) *(float4*)&o[oo] = make_float4(o0, o1, o2, o3);
        __half2 h0 = __floats2half2_rn(o0, o1);
        __half2 h1 = __floats2half2_rn(o2, o3);
        *(__half2*)&oh[oo] = h0;
        *(__half2*)&oh[oo + 2] = h1;
    }
}

// ---------------------------------------------------------------------------
// primitives
__device__ __forceinline__ void ldmx4(unsigned addr, unsigned r[4]) {
    asm volatile("ldmatrix.sync.aligned.m8n8.x4.shared.b16 {%0,%1,%2,%3}, [%4];"
                 : "=r"(r[0]), "=r"(r[1]), "=r"(r[2]), "=r"(r[3]) : "r"(addr));
}
__device__ __forceinline__ void ldmx4t(unsigned addr, unsigned r[4]) {
    asm volatile("ldmatrix.sync.aligned.m8n8.x4.trans.shared.b16 {%0,%1,%2,%3}, [%4];"
                 : "=r"(r[0]), "=r"(r[1]), "=r"(r[2]), "=r"(r[3]) : "r"(addr));
}
__device__ __forceinline__ void mma16816h(float d[4], const unsigned a[4],
                                          unsigned b0, unsigned b1) {
    asm volatile("mma.sync.aligned.m16n8k16.row.col.f32.f16.f16.f32 "
                 "{%0,%1,%2,%3},{%4,%5,%6,%7},{%8,%9},{%0,%1,%2,%3};"
                 : "+f"(d[0]), "+f"(d[1]), "+f"(d[2]), "+f"(d[3])
                 : "r"(a[0]), "r"(a[1]), "r"(a[2]), "r"(a[3]), "r"(b0), "r"(b1));
}
__device__ __forceinline__ void cp16(unsigned sa, const void* gm) {
    asm volatile("cp.async.cg.shared.global [%0], [%1], 16;" :: "r"(sa), "l"(gm));
}
__device__ __forceinline__ void cp_commit() { asm volatile("cp.async.commit_group;"); }
template <int N>
__device__ __forceinline__ void cp_wait() {
    asm volatile("cp.async.wait_group %0;" :: "n"(N));
}

// hgemm: K-chunk 64, pitch 72 halves (144B)
#define HP     72
#define HARR   (128 * HP)            // halves per tile array
#define HSTGB  (2 * HARR * 2)        // bytes per stage (A+B) = 36864
#define HSMEM  (2 * HSTGB)           // 73728

// ---------------------------------------------------------------------------
// fp16 NT GEMM: D[M,N] = A[M,K] @ (B[N,K])^T, fp32 accum.  K%64==0.
// MODE 0: +bias->fp32.  MODE 1: +bias,GELU->fp16.  MODE 2: +bias+res->fp32.
// MODE 3: plain->fp32.  MODE 4: +bias->fp16.
template <int MODE>
__global__ __launch_bounds__(256, 2)
void hgemm_k(const __half* __restrict__ A, const __half* __restrict__ B,
             const float* __restrict__ bias, const float* __restrict__ res,
             float* __restrict__ C, __half* __restrict__ O,
             int M, int N, int K) {
    extern __shared__ __align__(16) __half smbuf[];
    int tid = threadIdx.x, lane = tid & 31, wid = tid >> 5;
    int wm = wid >> 2, wn = wid & 3;
    int row0 = blockIdx.y * 128, col0 = blockIdx.x * 128;

    // copy coords: 1024 cp16 per array; 4 per thread per array
    int cr = tid >> 1;                     // rows 0..127 (2 thr/row)
    int cs = (tid & 1) * 4;                // segs 0..3 / 4..7
    size_t aoff = (size_t)(row0 + cr) * K + cs * 8;
    size_t boff = (size_t)(col0 + cr) * K + cs * 8;
    unsigned smbase = (unsigned)__cvta_generic_to_shared(smbuf);
    unsigned dA = smbase + (unsigned)(cr * HP + cs * 8) * 2;
    unsigned dB = dA + HARR * 2;

    int lr  = (lane & 7) + ((lane >> 3) & 1) * 8;
    int lcb = (lane >> 4) * 16;
    unsigned adA[4], adB[2];
#pragma unroll
    for (int i = 0; i < 4; i++)
        adA[i] = smbase + (unsigned)((wm * 64 + i * 16 + lr) * HP) * 2 + lcb;
#pragma unroll
    for (int p = 0; p < 2; p++)
        adB[p] = smbase + (unsigned)(HARR + (wn * 32 + p * 16 + lr) * HP) * 2 + lcb;

    float acc[4][4][4];
#pragma unroll
    for (int i = 0; i < 4; i++)
#pragma unroll
        for (int j = 0; j < 4; j++)
#pragma unroll
            for (int q = 0; q < 4; q++) acc[i][j][q] = 0.f;

    int nC = K >> 6;
    // prologue: chunk 0 -> stage 0
#pragma unroll
    for (int sgi = 0; sgi < 4; sgi++) {
        cp16(dA + sgi * 16, A + aoff + sgi * 8);
        cp16(dB + sgi * 16, B + boff + sgi * 8);
    }
    cp_commit();

    for (int c = 0; c < nC; c++) {
        if (c + 1 < nC) {
            unsigned so = (unsigned)((c + 1) & 1) * HSTGB;
            size_t ko = (size_t)(c + 1) << 6;
#pragma unroll
            for (int sgi = 0; sgi < 4; sgi++) {
                cp16(dA + so + sgi * 16, A + aoff + ko + sgi * 8);
                cp16(dB + so + sgi * 16, B + boff + ko + sgi * 8);
            }
            cp_commit();
            cp_wait<1>();
        } else {
            cp_wait<0>();
        }
        __syncthreads();

        unsigned so = (unsigned)(c & 1) * HSTGB;
#pragma unroll
        for (int s = 0; s < 4; s++) {
            unsigned ah[4][4], bh[2][4];
#pragma unroll
            for (int i = 0; i < 4; i++) ldmx4(adA[i] + so + s * 32, ah[i]);
#pragma unroll
            for (int p = 0; p < 2; p++) ldmx4(adB[p] + so + s * 32, bh[p]);
#pragma unroll
            for (int i = 0; i < 4; i++)
#pragma unroll
                for (int j = 0; j < 4; j++) {
                    int p = j >> 1, q = j & 1;
                    mma16816h(acc[i][j], ah[i], bh[p][q], bh[p][2 + q]);
                }
        }
        __syncthreads();
    }

    int g = lane >> 2, t2 = (lane & 3) * 2;
#pragma unroll
    for (int i = 0; i < 4; i++) {
        int rA = row0 + wm * 64 + i * 16 + g;
#pragma unroll
        for (int j = 0; j < 4; j++) {
            int cA = col0 + wn * 32 + j * 8 + t2;
            float v0 = acc[i][j][0], v1 = acc[i][j][1];
            float w0 = acc[i][j][2], w1 = acc[i][j][3];
            if (MODE != 3) {
                float b0 = bias[cA], b1 = bias[cA + 1];
                v0 += b0; v1 += b1; w0 += b0; w1 += b1;
            }
            if (MODE == 1) {
                v0 = 0.5f * v0 * (1.0f + erff(v0 * 0.70710678118654752440f));
                v1 = 0.5f * v1 * (1.0f + erff(v1 * 0.70710678118654752440f));
                w0 = 0.5f * w0 * (1.0f + erff(w0 * 0.70710678118654752440f));
                w1 = 0.5f * w1 * (1.0f + erff(w1 * 0.70710678118654752440f));
            }
            if (MODE == 1 || MODE == 4) {
                *(__half2*)&O[(size_t)rA * N + cA] = __floats2half2_rn(v0, v1);
                *(__half2*)&O[(size_t)(rA + 8) * N + cA] = __floats2half2_rn(w0, w1);
            } else {
                if (MODE == 2) {
                    float2 q0 = *(const float2*)&res[(size_t)rA * N + cA];
                    float2 q1 = *(const float2*)&res[(size_t)(rA + 8) * N + cA];
                    v0 += q0.x; v1 += q0.y; w0 += q1.x; w1 += q1.y;
                }
                *(float2*)&C[(size_t)rA * N + cA] = make_float2(v0, v1);
                *(float2*)&C[(size_t)(rA + 8) * N + cA] = make_float2(w0, w1);
            }
        }
    }
}

// ---------------------------------------------------------------------------
// Flash attention: q-tile 128, s-tile 64, fp16 mma, online softmax.
#define FKP   72
#define FQB   (128 * FKP * 2)
#define FKVST (64 * FKP * 2)
#define FSTG  (2 * FKVST)
#define FSMEM (FQB + 2 * FSTG)

__global__ __launch_bounds__(256)
void flash_k(const __half* __restrict__ qkv, __half* __restrict__ y) {
    extern __shared__ __align__(16) __half fsm[];
    int tid = threadIdx.x, lane = tid & 31, wid = tid >> 5;
    int qt = gridDim.x - 1 - blockIdx.x;   // heavy tiles first
    int h = blockIdx.y, b = blockIdx.z;
    int q0 = qt * 128;
    const __half* base = qkv + (size_t)b * TSEQ * (3 * CH);
    unsigned Qb = (unsigned)__cvta_generic_to_shared(fsm);
    unsigned KVb = Qb + FQB;

#pragma unroll
    for (int i = 0; i < 4; i++) {
        int idx = tid + i * 256;
        int row = idx >> 3, seg = idx & 7;
        cp16(Qb + row * 144 + seg * 16,
             base + (size_t)(q0 + row) * (3 * CH) + h * DH + seg * 8);
    }
#pragma unroll
    for (int i = 0; i < 2; i++) {
        int idx = tid + i * 256;
        int row = idx >> 3, seg = idx & 7;
        cp16(KVb + row * 144 + seg * 16,
             base + (size_t)row * (3 * CH) + CH + h * DH + seg * 8);
        cp16(KVb + FKVST + row * 144 + seg * 16,
             base + (size_t)row * (3 * CH) + 2 * CH + h * DH + seg * 8);
    }
    cp_commit();

    int lr  = (lane & 7) + ((lane >> 3) & 1) * 8;
    int lcb = (lane >> 4) * 16;
    unsigned qad[4];
#pragma unroll
    for (int kk = 0; kk < 4; kk++)
        qad[kk] = Qb + (unsigned)((wid * 16 + lr) * 144) + kk * 32 + lcb;

    unsigned Qf[4][4];
    float Oa[8][4];
#pragma unroll
    for (int j = 0; j < 8; j++)
#pragma unroll
        for (int q = 0; q < 4; q++) Oa[j][q] = 0.f;
    float m0 = -1e30f, m1 = -1e30f, l0 = 0.f, l1 = 0.f;

    int nT = 2 * (qt + 1);
    for (int t = 0; t < nT; t++) {
        if (t + 1 < nT) {
            unsigned kb = KVb + (unsigned)((t + 1) & 1) * FSTG;
            int s0n = (t + 1) * 64;
#pragma unroll
            for (int i = 0; i < 2; i++) {
                int idx = tid + i * 256;
                int row = idx >> 3, seg = idx & 7;
                cp16(kb + row * 144 + seg * 16,
                     base + (size_t)(s0n + row) * (3 * CH) + CH + h * DH + seg * 8);
                cp16(kb + FKVST + row * 144 + seg * 16,
                     base + (size_t)(s0n + row) * (3 * CH) + 2 * CH + h * DH + seg * 8);
            }
            cp_commit();
            cp_wait<1>();
        } else {
            cp_wait<0>();
        }
        __syncthreads();
        if (t == 0) {
#pragma unroll
            for (int kk = 0; kk < 4; kk++) ldmx4(qad[kk], Qf[kk]);
        }
        unsigned kb = KVb + (unsigned)(t & 1) * FSTG;

        float S[8][4];
#pragma unroll
        for (int j = 0; j < 8; j++)
#pragma unroll
            for (int q = 0; q < 4; q++) S[j][q] = 0.f;
#pragma unroll
        for (int kk = 0; kk < 4; kk++) {
            unsigned kf[4][4];
#pragma unroll
            for (int p = 0; p < 4; p++)
                ldmx4(kb + (unsigned)((p * 16 + lr) * 144) + kk * 32 + lcb, kf[p]);
#pragma unroll
            for (int p = 0; p < 4; p++)
#pragma unroll
                for (int qn = 0; qn < 2; qn++)
                    mma16816h(S[p * 2 + qn], Qf[kk], kf[p][qn], kf[p][2 + qn]);
        }

        int s0 = t * 64;
        int rg = q0 + wid * 16 + (lane >> 2);
        if (s0 + 63 > q0 + wid * 16) {
#pragma unroll
            for (int j = 0; j < 8; j++) {
                int sc = s0 + j * 8 + (lane & 3) * 2;
                if (sc > rg)     S[j][0] = -1e30f;
                if (sc + 1 > rg) S[j][1] = -1e30f;
                if (sc > rg + 8)     S[j][2] = -1e30f;
                if (sc + 1 > rg + 8) S[j][3] = -1e30f;
            }
        }
        float mx0 = -1e30f, mx1 = -1e30f;
#pragma unroll
        for (int j = 0; j < 8; j++) {
            mx0 = fmaxf(mx0, fmaxf(S[j][0], S[j][1]));
            mx1 = fmaxf(mx1, fmaxf(S[j][2], S[j][3]));
        }
        mx0 = fmaxf(mx0, __shfl_xor_sync(0xffffffffu, mx0, 1));
        mx0 = fmaxf(mx0, __shfl_xor_sync(0xffffffffu, mx0, 2));
        mx1 = fmaxf(mx1, __shfl_xor_sync(0xffffffffu, mx1, 1));
        mx1 = fmaxf(mx1, __shfl_xor_sync(0xffffffffu, mx1, 2));
        mx0 *= 0.125f; mx1 *= 0.125f;
        float mn0 = fmaxf(m0, mx0), mn1 = fmaxf(m1, mx1);
        float a0 = __expf(m0 - mn0), a1 = __expf(m1 - mn1);
        m0 = mn0; m1 = mn1;
        float rs0 = 0.f, rs1 = 0.f;
        __half2 P[8][2];
#pragma unroll
        for (int j = 0; j < 8; j++) {
            float p0 = __expf(S[j][0] * 0.125f - m0);
            float p1 = __expf(S[j][1] * 0.125f - m0);
            float p2 = __expf(S[j][2] * 0.125f - m1);
            float p3 = __expf(S[j][3] * 0.125f - m1);
            rs0 += p0 + p1; rs1 += p2 + p3;
            P[j][0] = __floats2half2_rn(p0, p1);
            P[j][1] = __floats2half2_rn(p2, p3);
        }
        l0 = l0 * a0 + rs0; l1 = l1 * a1 + rs1;
#pragma unroll
        for (int j = 0; j < 8; j++) {
            Oa[j][0] *= a0; Oa[j][1] *= a0; Oa[j][2] *= a1; Oa[j][3] *= a1;
        }
        unsigned vb = kb + FKVST;
#pragma unroll
        for (int kt = 0; kt < 4; kt++) {
            unsigned vf[4][4];
#pragma unroll
            for (int dg = 0; dg < 4; dg++)
                ldmx4t(vb + (unsigned)((kt * 16 + lr) * 144) + dg * 32 + lcb, vf[dg]);
            unsigned pa[4];
            pa[0] = *(unsigned*)&P[2 * kt][0];
            pa[1] = *(unsigned*)&P[2 * kt][1];
            pa[2] = *(unsigned*)&P[2 * kt + 1][0];
            pa[3] = *(unsigned*)&P[2 * kt + 1][1];
#pragma unroll
            for (int dg = 0; dg < 4; dg++) {
                mma16816h(Oa[dg * 2 + 0], pa, vf[dg][0], vf[dg][1]);
                mma16816h(Oa[dg * 2 + 1], pa, vf[dg][2], vf[dg][3]);
            }
        }
        __syncthreads();
    }

    l0 += __shfl_xor_sync(0xffffffffu, l0, 1);
    l0 += __shfl_xor_sync(0xffffffffu, l0, 2);
    l1 += __shfl_xor_sync(0xffffffffu, l1, 1);
    l1 += __shfl_xor_sync(0xffffffffu, l1, 2);
    float inv0 = 1.0f / l0, inv1 = 1.0f / l1;
    int g = lane >> 2, t2 = (lane & 3) * 2;
    int rowg = q0 + wid * 16 + g;
#pragma unroll
    for (int j = 0; j < 8; j++) {
        int d = h * DH + j * 8 + t2;
        *(__half2*)&y[(size_t)(b * TSEQ + rowg) * CH + d] =
            __floats2half2_rn(Oa[j][0] * inv0, Oa[j][1] * inv0);
        *(__half2*)&y[(size_t)(b * TSEQ + rowg + 8) * CH + d] =
            __floats2half2_rn(Oa[j][2] * inv1, Oa[j][3] * inv1);
    }
}

// ---------------------------------------------------------------------------
__global__ void zero_loss_k(float* num, float* den) { *num = 0.f; *den = 0.f; }

// single-pass online log-sum-exp NLL (float4 reads)
__global__ void loss_k(const float* __restrict__ logits, const int* __restrict__ tg,
                       float* num, float* den) {
    __shared__ float rm[256], rs[256];
    int row = blockIdx.x;
    const float4* lr4 = (const float4*)(logits + (size_t)row * VOC);
    float m = -3.0e38f, s = 0.f;
    for (int j = threadIdx.x; j < VOC / 4; j += 256) {
        float4 v = lr4[j];
        float vm = fmaxf(fmaxf(v.x, v.y), fmaxf(v.z, v.w));
        if (vm > m) { s = s * __expf(m - vm); m = vm; }
        s += __expf(v.x - m) + __expf(v.y - m) + __expf(v.z - m) + __expf(v.w - m);
    }
    rm[threadIdx.x] = m; rs[threadIdx.x] = s;
    __syncthreads();
    for (int off = 128; off > 0; off >>= 1) {
        if (threadIdx.x < off) {
            float m2 = rm[threadIdx.x + off], s2 = rs[threadIdx.x + off];
            float m1 = rm[threadIdx.x], s1 = rs[threadIdx.x];
            float mn = fmaxf(m1, m2);
            rs[threadIdx.x] = s1 * __expf(m1 - mn) + s2 * __expf(m2 - mn);
            rm[threadIdx.x] = mn;
        }
        __syncthreads();
    }
    if (threadIdx.x == 0) {
        int t = tg[row];
        if (t != 0) {
            float lse = rm[0] + logf(rs[0]);
            atomicAdd(num, lse - logits[(size_t)row * VOC + t]);
            atomicAdd(den, 1.0f);
        }
    }
}

__global__ void final_loss_k(const float* num, const float* den, float* out) {
    out[0] = *num / fmaxf(*den, 1.0f);
}

// ---------------------------------------------------------------------------
extern "C" void kernel_launch(void* const* d_in, const int* in_sizes, int n_in,
                              void* d_out, int out_size) {
    const int*   idx     = (const int*)d_in[0];
    const int*   targets = (const int*)d_in[1];
    const float* wte     = (const float*)d_in[2];
    const float* wpe     = (const float*)d_in[3];
    const float* ln1_g   = (const float*)d_in[4];
    const float* ln1_b   = (const float*)d_in[5];
    const float* attn_w  = (const float*)d_in[6];
    const float* attn_b  = (const float*)d_in[7];
    const float* proj_w  = (const float*)d_in[8];
    const float* proj_b  = (const float*)d_in[9];
    const float* ln2_g   = (const float*)d_in[10];
    const float* ln2_b   = (const float*)d_in[11];
    const float* fc_w    = (const float*)d_in[12];
    const float* fc_b    = (const float*)d_in[13];
    const float* fc2_w   = (const float*)d_in[14];
    const float* fc2_b   = (const float*)d_in[15];
    const float* lnf_g   = (const float*)d_in[16];
    const float* lnf_b   = (const float*)d_in[17];
    float* out = (float*)d_out;

    float *x, *h, *pnum, *pden;
    __half *qkv_h, *h_h, *y_h, *m_h, *wt_h, *wte_h;
    cudaGetSymbolAddress((void**)&x, g_x);
    cudaGetSymbolAddress((void**)&h, g_hf);
    cudaGetSymbolAddress((void**)&qkv_h, g_qkv_h);
    cudaGetSymbolAddress((void**)&h_h, g_h_h);
    cudaGetSymbolAddress((void**)&y_h, g_y_h);
    cudaGetSymbolAddress((void**)&m_h, g_m_h);
    cudaGetSymbolAddress((void**)&wt_h, g_wt_h);
    cudaGetSymbolAddress((void**)&wte_h, g_wte_h);
    cudaGetSymbolAddress((void**)&pnum, g_num);
    cudaGetSymbolAddress((void**)&pden, g_den);

    const size_t LOGN = (size_t)BT * VOC;
    float* out_loss = out + LOGN;
    float* out_x    = out + LOGN + 1;  // 4B-aligned only: scalar access

    cudaFuncSetAttribute(hgemm_k<0>, cudaFuncAttributeMaxDynamicSharedMemorySize, HSMEM);
    cudaFuncSetAttribute(hgemm_k<1>, cudaFuncAttributeMaxDynamicSharedMemorySize, HSMEM);
    cudaFuncSetAttribute(hgemm_k<2>, cudaFuncAttributeMaxDynamicSharedMemorySize, HSMEM);
    cudaFuncSetAttribute(hgemm_k<3>, cudaFuncAttributeMaxDynamicSharedMemorySize, HSMEM);
    cudaFuncSetAttribute(hgemm_k<4>, cudaFuncAttributeMaxDynamicSharedMemorySize, HSMEM);
    cudaFuncSetAttribute(flash_k, cudaFuncAttributeMaxDynamicSharedMemorySize, FSMEM);

    dim3 tblk(32, 8);

    // ---- weight preprocessing (batched over layers) ----
    conv_k<<<(VOC * CH / 4 + 255) / 256, 256>>>((const float4*)wte, wte_h, VOC * CH / 4);
    tconv_k<<<dim3(2304 / 32, 768 / 32, NLAY), tblk>>>(
        attn_w, wt_h + W_ATTN_OFF, 768, 2304, (size_t)W_ATTN_SZ, (size_t)W_ATTN_SZ);
    tconv_k<<<dim3(768 / 32, 768 / 32, NLAY), tblk>>>(
        proj_w, wt_h + W_PROJ_OFF, 768, 768, (size_t)W_PROJ_SZ, (size_t)W_PROJ_SZ);
    tconv_k<<<dim3(3072 / 32, 768 / 32, NLAY), tblk>>>(
        fc_w, wt_h + W_FC_OFF, 768, 3072, (size_t)W_FC_SZ, (size_t)W_FC_SZ);
    tconv_k<<<dim3(768 / 32, 3072 / 32, NLAY), tblk>>>(
        fc2_w, wt_h + W_FC2_OFF, 3072, 768, (size_t)W_FC2_SZ, (size_t)W_FC2_SZ);

    embed_k<<<BT, 256>>>(idx, wte, wpe, x);

    for (int l = 0; l < NLAY; l++) {
        const __half* wa = wt_h + W_ATTN_OFF + (size_t)l * W_ATTN_SZ;
        const __half* wp = wt_h + W_PROJ_OFF + (size_t)l * W_PROJ_SZ;
        const __half* wf = wt_h + W_FC_OFF + (size_t)l * W_FC_SZ;
        const __half* w2 = wt_h + W_FC2_OFF + (size_t)l * W_FC2_SZ;

        ln_k<0><<<BT / 8, 256>>>(x, ln1_g + l * CH, ln1_b + l * CH, nullptr, h_h);
        hgemm_k<4><<<dim3(2304 / 128, BT / 128), 256, HSMEM>>>(
            h_h, wa, attn_b + (size_t)l * 3 * CH, nullptr, nullptr, qkv_h, BT, 3 * CH, CH);
        flash_k<<<dim3(TSEQ / 128, NH, 4), 256, FSMEM>>>(qkv_h, y_h);
        hgemm_k<2><<<dim3(CH / 128, BT / 128), 256, HSMEM>>>(
            y_h, wp, proj_b + (size_t)l * CH, x, x, nullptr, BT, CH, CH);
        ln_k<0><<<BT / 8, 256>>>(x, ln2_g + l * CH, ln2_b + l * CH, nullptr, h_h);
        hgemm_k<1><<<dim3(4 * CH / 128, BT / 128), 256, HSMEM>>>(
            h_h, wf, fc_b + (size_t)l * 4 * CH, nullptr, nullptr, m_h, BT, 4 * CH, CH);
        hgemm_k<2><<<dim3(CH / 128, BT / 128), 256, HSMEM>>>(
            m_h, w2, fc2_b + (size_t)l * CH, x, x, nullptr, BT, CH, 4 * CH);
    }

    ln_k<1><<<BT / 8, 256>>>(x, lnf_g, lnf_b, h, h_h);
    copy_k<<<(BT * CH + 255) / 256, 256>>>(h, out_x, BT * CH);
    hgemm_k<3><<<dim3(VOC / 128, BT / 128), 256, HSMEM>>>(
        h_h, wte_h, nullptr, nullptr, out, nullptr, BT, VOC, CH);
    zero_loss_k<<<1, 1>>>(pnum, pden);
    loss_k<<<BT, 256>>>(out, targets, pnum, pden);
    final_loss_k<<<1, 1>>>(pnum, pden, out_loss);
}

// round 16
// speedup vs baseline: 1.1964x; 1.1964x over previous
#include <cuda_runtime.h>
#include <cuda_bf16.h>
#include <cuda_fp16.h>
#include <math.h>
#include <stdint.h>

// ---------------------------------------------------------------------------
// GPT-2 small forward: L=6, C=768, H=12, D=64, B=4, T=1024, V=32000
// Output layout: logits [4096*32000] | loss [1] | x_final [4096*768]
// Round 16: hgemm reverted to round-14 (K-chunk 32) after K-64 regression;
// keep warp-per-row LN and float4 loss.  fp16 mma GEMMs + flash attention.
// ---------------------------------------------------------------------------

#define BT   4096
#define CH   768
#define NH   12
#define DH   64
#define TSEQ 1024
#define VOC  32000
#define NLAY 6

#define W_ATTN_OFF 0
#define W_ATTN_SZ  (2304 * 768)
#define W_PROJ_OFF (W_ATTN_OFF + 6 * W_ATTN_SZ)
#define W_PROJ_SZ  (768 * 768)
#define W_FC_OFF   (W_PROJ_OFF + 6 * W_PROJ_SZ)
#define W_FC_SZ    (3072 * 768)
#define W_FC2_OFF  (W_FC_OFF + 6 * W_FC_SZ)
#define W_FC2_SZ   (768 * 3072)
#define W_TOTAL    (W_FC2_OFF + 6 * W_FC2_SZ)

// Scratch (device globals: no allocation allowed)
__device__ float g_x[BT * CH];
__device__ float g_hf[BT * CH];
__device__ __half g_qkv_h[BT * 3 * CH];
__device__ __half g_h_h[BT * CH];
__device__ __half g_y_h[BT * CH];
__device__ __half g_m_h[BT * 4 * CH];
__device__ __half g_wt_h[W_TOTAL];
__device__ __half g_wte_h[VOC * CH];
__device__ float g_num;
__device__ float g_den;

// ---------------------------------------------------------------------------
__global__ void conv_k(const float4* __restrict__ src, __half* __restrict__ dst, int n4) {
    int i = blockIdx.x * 256 + threadIdx.x;
    if (i < n4) {
        float4 v = src[i];
        *(__half2*)&dst[i * 4] = __floats2half2_rn(v.x, v.y);
        *(__half2*)&dst[i * 4 + 2] = __floats2half2_rn(v.z, v.w);
    }
}

// batched transpose + convert: W[l][K,N] fp32 -> T[l][N,K] fp16, blockIdx.z = layer
__global__ void tconv_k(const float* __restrict__ W, __half* __restrict__ T,
                        int K, int N, size_t wstride, size_t tstride) {
    __shared__ float s[32][33];
    int n0 = blockIdx.x * 32, k0 = blockIdx.y * 32;
    const float* Wl = W + (size_t)blockIdx.z * wstride;
    __half* Tl = T + (size_t)blockIdx.z * tstride;
    int tx = threadIdx.x, ty = threadIdx.y;
#pragma unroll
    for (int i = 0; i < 4; i++)
        s[ty + i * 8][tx] = Wl[(size_t)(k0 + ty + i * 8) * N + n0 + tx];
    __syncthreads();
#pragma unroll
    for (int i = 0; i < 4; i++)
        Tl[(size_t)(n0 + ty + i * 8) * K + k0 + tx] = __float2half(s[tx][ty + i * 8]);
}

// ---------------------------------------------------------------------------
__global__ void embed_k(const int* __restrict__ idx, const float* __restrict__ wte,
                        const float* __restrict__ wpe, float* __restrict__ x) {
    int row = blockIdx.x;
    int t = row & (TSEQ - 1);
    int tok = idx[row];
    const float* a = wte + (size_t)tok * CH;
    const float* b = wpe + (size_t)t * CH;
    float* o = x + (size_t)row * CH;
    for (int c = threadIdx.x; c < CH; c += blockDim.x) o[c] = a[c] + b[c];
}

__global__ void copy_k(const float* __restrict__ src, float* __restrict__ dst, int n) {
    int i = blockIdx.x * blockDim.x + threadIdx.x;
    if (i < n) dst[i] = src[i];
}

// LayerNorm: one WARP per row, float4 loads, shfl reductions, no block sync.
template <int WF32>
__global__ void ln_k(const float* __restrict__ x, const float* __restrict__ g,
                     const float* __restrict__ b, float* __restrict__ o,
                     __half* __restrict__ oh) {
    int row = blockIdx.x * 8 + (threadIdx.x >> 5);
    int lane = threadIdx.x & 31;
    const float4* xr = (const float4*)(x + (size_t)row * CH);
    float4 v[6];
    float s = 0.f, s2 = 0.f;
#pragma unroll
    for (int i = 0; i < 6; i++) {
        v[i] = xr[lane + i * 32];
        s  += v[i].x + v[i].y + v[i].z + v[i].w;
        s2 += v[i].x * v[i].x + v[i].y * v[i].y + v[i].z * v[i].z + v[i].w * v[i].w;
    }
#pragma unroll
    for (int off = 16; off > 0; off >>= 1) {
        s  += __shfl_xor_sync(0xffffffffu, s, off);
        s2 += __shfl_xor_sync(0xffffffffu, s2, off);
    }
    float mean = s * (1.0f / CH);
    float var  = s2 * (1.0f / CH) - mean * mean;
    float rstd = rsqrtf(var + 1e-5f);
    const float4* gg = (const float4*)g;
    const float4* bb = (const float4*)b;
#pragma unroll
    for (int i = 0; i < 6; i++) {
        int c4 = lane + i * 32;
        float4 gv = gg[c4], bv = bb[c4];
        float o0 = (v[i].x - mean) * rstd * gv.x + bv.x;
        float o1 = (v[i].y - mean) * rstd * gv.y + bv.y;
        float o2 = (v[i].z - mean) * rstd * gv.z + bv.z;
        float o3 = (v[i].w - mean) * rstd * gv.w + bv.w;
        size_t oo = (size_t)row * CH + c4 * 4;
        if (WF32) *(float4*)&o[oo] = make_float4(o0, o1, o2, o3);
        *(__half2*)&oh[oo] = __floats2half2_rn(o0, o1);
        *(__half2*)&oh[oo + 2] = __floats2half2_rn(o2, o3);
    }
}

// ---------------------------------------------------------------------------
// primitives
__device__ __forceinline__ void ldmx4(unsigned addr, unsigned r[4]) {
    asm volatile("ldmatrix.sync.aligned.m8n8.x4.shared.b16 {%0,%1,%2,%3}, [%4];"
                 : "=r"(r[0]), "=r"(r[1]), "=r"(r[2]), "=r"(r[3]) : "r"(addr));
}
__device__ __forceinline__ void ldmx4t(unsigned addr, unsigned r[4]) {
    asm volatile("ldmatrix.sync.aligned.m8n8.x4.trans.shared.b16 {%0,%1,%2,%3}, [%4];"
                 : "=r"(r[0]), "=r"(r[1]), "=r"(r[2]), "=r"(r[3]) : "r"(addr));
}
__device__ __forceinline__ void mma16816h(float d[4], const unsigned a[4],
                                          unsigned b0, unsigned b1) {
    asm volatile("mma.sync.aligned.m16n8k16.row.col.f32.f16.f16.f32 "
                 "{%0,%1,%2,%3},{%4,%5,%6,%7},{%8,%9},{%0,%1,%2,%3};"
                 : "+f"(d[0]), "+f"(d[1]), "+f"(d[2]), "+f"(d[3])
                 : "r"(a[0]), "r"(a[1]), "r"(a[2]), "r"(a[3]), "r"(b0), "r"(b1));
}
__device__ __forceinline__ void cp16(unsigned sa, const void* gm) {
    asm volatile("cp.async.cg.shared.global [%0], [%1], 16;" :: "r"(sa), "l"(gm));
}
__device__ __forceinline__ void cp_commit() { asm volatile("cp.async.commit_group;"); }
template <int N>
__device__ __forceinline__ void cp_wait() {
    asm volatile("cp.async.wait_group %0;" :: "n"(N));
}

#define SPITCH 40
#define ARR    (128 * SPITCH)
#define STGB   (2 * ARR * 2)
#define HSMEM  (2 * STGB)

// ---------------------------------------------------------------------------
// fp16 NT GEMM: D[M,N] = A[M,K] @ (B[N,K])^T, fp32 accum.  (round-14 version)
// MODE 0: +bias->fp32.  MODE 1: +bias,GELU->fp16.  MODE 2: +bias+res->fp32.
// MODE 3: plain->fp32.  MODE 4: +bias->fp16.
template <int MODE>
__global__ __launch_bounds__(256, 2)
void hgemm_k(const __half* __restrict__ A, const __half* __restrict__ B,
             const float* __restrict__ bias, const float* __restrict__ res,
             float* __restrict__ C, __half* __restrict__ O,
             int M, int N, int K) {
    extern __shared__ __align__(16) __half smbuf[];
    int tid = threadIdx.x, lane = tid & 31, wid = tid >> 5;
    int wm = wid >> 2, wn = wid & 3;
    int row0 = blockIdx.y * 128, col0 = blockIdx.x * 128;

    int r0 = tid >> 2, sg = (tid & 3) * 8;
    size_t aoff0 = (size_t)(row0 + r0) * K + sg;
    size_t aoff1 = aoff0 + (size_t)64 * K;
    size_t boff0 = (size_t)(col0 + r0) * K + sg;
    size_t boff1 = boff0 + (size_t)64 * K;
    int sm0 = r0 * SPITCH + sg, sm1 = sm0 + 64 * SPITCH;

    unsigned smbase = (unsigned)__cvta_generic_to_shared(smbuf);
    unsigned dA0 = smbase + sm0 * 2,         dA1 = smbase + sm1 * 2;
    unsigned dB0 = smbase + (ARR + sm0) * 2, dB1 = smbase + (ARR + sm1) * 2;

    int lr  = (lane & 7) + ((lane >> 3) & 1) * 8;
    int lcb = (lane >> 4) * 16;
    unsigned adA[4], adB[2];
#pragma unroll
    for (int i = 0; i < 4; i++) {
        int rr = wm * 64 + i * 16 + lr;
        adA[i] = smbase + (unsigned)(rr * SPITCH) * 2 + lcb;
    }
#pragma unroll
    for (int p = 0; p < 2; p++) {
        int rr = wn * 32 + p * 16 + lr;
        adB[p] = smbase + (unsigned)(ARR + rr * SPITCH) * 2 + lcb;
    }

    float acc[4][4][4];
#pragma unroll
    for (int i = 0; i < 4; i++)
#pragma unroll
        for (int j = 0; j < 4; j++)
#pragma unroll
            for (int q = 0; q < 4; q++) acc[i][j][q] = 0.f;

    int nC = K >> 5;
    cp16(dA0, A + aoff0); cp16(dA1, A + aoff1);
    cp16(dB0, B + boff0); cp16(dB1, B + boff1);
    cp_commit();

    for (int c = 0; c < nC; c++) {
        if (c + 1 < nC) {
            unsigned so = (unsigned)((c + 1) & 1) * STGB;
            size_t ko = (size_t)(c + 1) << 5;
            cp16(dA0 + so, A + aoff0 + ko); cp16(dA1 + so, A + aoff1 + ko);
            cp16(dB0 + so, B + boff0 + ko); cp16(dB1 + so, B + boff1 + ko);
            cp_commit();
            cp_wait<1>();
        } else {
            cp_wait<0>();
        }
        __syncthreads();

        unsigned so = (unsigned)(c & 1) * STGB;
#pragma unroll
        for (int s = 0; s < 2; s++) {
            unsigned ah[4][4], bh[2][4];
#pragma unroll
            for (int i = 0; i < 4; i++) ldmx4(adA[i] + so + s * 32, ah[i]);
#pragma unroll
            for (int p = 0; p < 2; p++) ldmx4(adB[p] + so + s * 32, bh[p]);
#pragma unroll
            for (int i = 0; i < 4; i++)
#pragma unroll
                for (int j = 0; j < 4; j++) {
                    int p = j >> 1, q = j & 1;
                    mma16816h(acc[i][j], ah[i], bh[p][q], bh[p][2 + q]);
                }
        }
        __syncthreads();
    }

    int g = lane >> 2, t2 = (lane & 3) * 2;
#pragma unroll
    for (int i = 0; i < 4; i++) {
        int rA = row0 + wm * 64 + i * 16 + g;
#pragma unroll
        for (int j = 0; j < 4; j++) {
            int cA = col0 + wn * 32 + j * 8 + t2;
            float v0 = acc[i][j][0], v1 = acc[i][j][1];
            float w0 = acc[i][j][2], w1 = acc[i][j][3];
            if (MODE != 3) {
                float b0 = bias[cA], b1 = bias[cA + 1];
                v0 += b0; v1 += b1; w0 += b0; w1 += b1;
            }
            if (MODE == 1) {
                v0 = 0.5f * v0 * (1.0f + erff(v0 * 0.70710678118654752440f));
                v1 = 0.5f * v1 * (1.0f + erff(v1 * 0.70710678118654752440f));
                w0 = 0.5f * w0 * (1.0f + erff(w0 * 0.70710678118654752440f));
                w1 = 0.5f * w1 * (1.0f + erff(w1 * 0.70710678118654752440f));
            }
            if (MODE == 1 || MODE == 4) {
                *(__half2*)&O[(size_t)rA * N + cA] = __floats2half2_rn(v0, v1);
                *(__half2*)&O[(size_t)(rA + 8) * N + cA] = __floats2half2_rn(w0, w1);
            } else {
                if (MODE == 2) {
                    float2 q0 = *(const float2*)&res[(size_t)rA * N + cA];
                    float2 q1 = *(const float2*)&res[(size_t)(rA + 8) * N + cA];
                    v0 += q0.x; v1 += q0.y; w0 += q1.x; w1 += q1.y;
                }
                *(float2*)&C[(size_t)rA * N + cA] = make_float2(v0, v1);
                *(float2*)&C[(size_t)(rA + 8) * N + cA] = make_float2(w0, w1);
            }
        }
    }
}

// ---------------------------------------------------------------------------
// Flash attention: q-tile 128, s-tile 64, fp16 mma, online softmax.
#define FKP   72
#define FQB   (128 * FKP * 2)
#define FKVST (64 * FKP * 2)
#define FSTG  (2 * FKVST)
#define FSMEM (FQB + 2 * FSTG)

__global__ __launch_bounds__(256)
void flash_k(const __half* __restrict__ qkv, __half* __restrict__ y) {
    extern __shared__ __align__(16) __half fsm[];
    int tid = threadIdx.x, lane = tid & 31, wid = tid >> 5;
    int qt = gridDim.x - 1 - blockIdx.x;   // heavy tiles first
    int h = blockIdx.y, b = blockIdx.z;
    int q0 = qt * 128;
    const __half* base = qkv + (size_t)b * TSEQ * (3 * CH);
    unsigned Qb = (unsigned)__cvta_generic_to_shared(fsm);
    unsigned KVb = Qb + FQB;

#pragma unroll
    for (int i = 0; i < 4; i++) {
        int idx = tid + i * 256;
        int row = idx >> 3, seg = idx & 7;
        cp16(Qb + row * 144 + seg * 16,
             base + (size_t)(q0 + row) * (3 * CH) + h * DH + seg * 8);
    }
#pragma unroll
    for (int i = 0; i < 2; i++) {
        int idx = tid + i * 256;
        int row = idx >> 3, seg = idx & 7;
        cp16(KVb + row * 144 + seg * 16,
             base + (size_t)row * (3 * CH) + CH + h * DH + seg * 8);
        cp16(KVb + FKVST + row * 144 + seg * 16,
             base + (size_t)row * (3 * CH) + 2 * CH + h * DH + seg * 8);
    }
    cp_commit();

    int lr  = (lane & 7) + ((lane >> 3) & 1) * 8;
    int lcb = (lane >> 4) * 16;
    unsigned qad[4];
#pragma unroll
    for (int kk = 0; kk < 4; kk++)
        qad[kk] = Qb + (unsigned)((wid * 16 + lr) * 144) + kk * 32 + lcb;

    unsigned Qf[4][4];
    float Oa[8][4];
#pragma unroll
    for (int j = 0; j < 8; j++)
#pragma unroll
        for (int q = 0; q < 4; q++) Oa[j][q] = 0.f;
    float m0 = -1e30f, m1 = -1e30f, l0 = 0.f, l1 = 0.f;

    int nT = 2 * (qt + 1);
    for (int t = 0; t < nT; t++) {
        if (t + 1 < nT) {
            unsigned kb = KVb + (unsigned)((t + 1) & 1) * FSTG;
            int s0n = (t + 1) * 64;
#pragma unroll
            for (int i = 0; i < 2; i++) {
                int idx = tid + i * 256;
                int row = idx >> 3, seg = idx & 7;
                cp16(kb + row * 144 + seg * 16,
                     base + (size_t)(s0n + row) * (3 * CH) + CH + h * DH + seg * 8);
                cp16(kb + FKVST + row * 144 + seg * 16,
                     base + (size_t)(s0n + row) * (3 * CH) + 2 * CH + h * DH + seg * 8);
            }
            cp_commit();
            cp_wait<1>();
        } else {
            cp_wait<0>();
        }
        __syncthreads();
        if (t == 0) {
#pragma unroll
            for (int kk = 0; kk < 4; kk++) ldmx4(qad[kk], Qf[kk]);
        }
        unsigned kb = KVb + (unsigned)(t & 1) * FSTG;

        float S[8][4];
#pragma unroll
        for (int j = 0; j < 8; j++)
#pragma unroll
            for (int q = 0; q < 4; q++) S[j][q] = 0.f;
#pragma unroll
        for (int kk = 0; kk < 4; kk++) {
            unsigned kf[4][4];
#pragma unroll
            for (int p = 0; p < 4; p++)
                ldmx4(kb + (unsigned)((p * 16 + lr) * 144) + kk * 32 + lcb, kf[p]);
#pragma unroll
            for (int p = 0; p < 4; p++)
#pragma unroll
                for (int qn = 0; qn < 2; qn++)
                    mma16816h(S[p * 2 + qn], Qf[kk], kf[p][qn], kf[p][2 + qn]);
        }

        int s0 = t * 64;
        int rg = q0 + wid * 16 + (lane >> 2);
        if (s0 + 63 > q0 + wid * 16) {
#pragma unroll
            for (int j = 0; j < 8; j++) {
                int sc = s0 + j * 8 + (lane & 3) * 2;
                if (sc > rg)     S[j][0] = -1e30f;
                if (sc + 1 > rg) S[j][1] = -1e30f;
                if (sc > rg + 8)     S[j][2] = -1e30f;
                if (sc + 1 > rg + 8) S[j][3] = -1e30f;
            }
        }
        float mx0 = -1e30f, mx1 = -1e30f;
#pragma unroll
        for (int j = 0; j < 8; j++) {
            mx0 = fmaxf(mx0, fmaxf(S[j][0], S[j][1]));
            mx1 = fmaxf(mx1, fmaxf(S[j][2], S[j][3]));
        }
        mx0 = fmaxf(mx0, __shfl_xor_sync(0xffffffffu, mx0, 1));
        mx0 = fmaxf(mx0, __shfl_xor_sync(0xffffffffu, mx0, 2));
        mx1 = fmaxf(mx1, __shfl_xor_sync(0xffffffffu, mx1, 1));
        mx1 = fmaxf(mx1, __shfl_xor_sync(0xffffffffu, mx1, 2));
        mx0 *= 0.125f; mx1 *= 0.125f;
        float mn0 = fmaxf(m0, mx0), mn1 = fmaxf(m1, mx1);
        float a0 = __expf(m0 - mn0), a1 = __expf(m1 - mn1);
        m0 = mn0; m1 = mn1;
        float rs0 = 0.f, rs1 = 0.f;
        __half2 P[8][2];
#pragma unroll
        for (int j = 0; j < 8; j++) {
            float p0 = __expf(S[j][0] * 0.125f - m0);
            float p1 = __expf(S[j][1] * 0.125f - m0);
            float p2 = __expf(S[j][2] * 0.125f - m1);
            float p3 = __expf(S[j][3] * 0.125f - m1);
            rs0 += p0 + p1; rs1 += p2 + p3;
            P[j][0] = __floats2half2_rn(p0, p1);
            P[j][1] = __floats2half2_rn(p2, p3);
        }
        l0 = l0 * a0 + rs0; l1 = l1 * a1 + rs1;
#pragma unroll
        for (int j = 0; j < 8; j++) {
            Oa[j][0] *= a0; Oa[j][1] *= a0; Oa[j][2] *= a1; Oa[j][3] *= a1;
        }
        unsigned vb = kb + FKVST;
#pragma unroll
        for (int kt = 0; kt < 4; kt++) {
            unsigned vf[4][4];
#pragma unroll
            for (int dg = 0; dg < 4; dg++)
                ldmx4t(vb + (unsigned)((kt * 16 + lr) * 144) + dg * 32 + lcb, vf[dg]);
            unsigned pa[4];
            pa[0] = *(unsigned*)&P[2 * kt][0];
            pa[1] = *(unsigned*)&P[2 * kt][1];
            pa[2] = *(unsigned*)&P[2 * kt + 1][0];
            pa[3] = *(unsigned*)&P[2 * kt + 1][1];
#pragma unroll
            for (int dg = 0; dg < 4; dg++) {
                mma16816h(Oa[dg * 2 + 0], pa, vf[dg][0], vf[dg][1]);
                mma16816h(Oa[dg * 2 + 1], pa, vf[dg][2], vf[dg][3]);
            }
        }
        __syncthreads();
    }

    l0 += __shfl_xor_sync(0xffffffffu, l0, 1);
    l0 += __shfl_xor_sync(0xffffffffu, l0, 2);
    l1 += __shfl_xor_sync(0xffffffffu, l1, 1);
    l1 += __shfl_xor_sync(0xffffffffu, l1, 2);
    float inv0 = 1.0f / l0, inv1 = 1.0f / l1;
    int g = lane >> 2, t2 = (lane & 3) * 2;
    int rowg = q0 + wid * 16 + g;
#pragma unroll
    for (int j = 0; j < 8; j++) {
        int d = h * DH + j * 8 + t2;
        *(__half2*)&y[(size_t)(b * TSEQ + rowg) * CH + d] =
            __floats2half2_rn(Oa[j][0] * inv0, Oa[j][1] * inv0);
        *(__half2*)&y[(size_t)(b * TSEQ + rowg + 8) * CH + d] =
            __floats2half2_rn(Oa[j][2] * inv1, Oa[j][3] * inv1);
    }
}

// ---------------------------------------------------------------------------
__global__ void zero_loss_k(float* num, float* den) { *num = 0.f; *den = 0.f; }

// single-pass online log-sum-exp NLL (float4 reads)
__global__ void loss_k(const float* __restrict__ logits, const int* __restrict__ tg,
                       float* num, float* den) {
    __shared__ float rm[256], rs[256];
    int row = blockIdx.x;
    const float4* lr4 = (const float4*)(logits + (size_t)row * VOC);
    float m = -3.0e38f, s = 0.f;
    for (int j = threadIdx.x; j < VOC / 4; j += 256) {
        float4 v = lr4[j];
        float vm = fmaxf(fmaxf(v.x, v.y), fmaxf(v.z, v.w));
        if (vm > m) { s = s * __expf(m - vm); m = vm; }
        s += __expf(v.x - m) + __expf(v.y - m) + __expf(v.z - m) + __expf(v.w - m);
    }
    rm[threadIdx.x] = m; rs[threadIdx.x] = s;
    __syncthreads();
    for (int off = 128; off > 0; off >>= 1) {
        if (threadIdx.x < off) {
            float m2 = rm[threadIdx.x + off], s2 = rs[threadIdx.x + off];
            float m1 = rm[threadIdx.x], s1 = rs[threadIdx.x];
            float mn = fmaxf(m1, m2);
            rs[threadIdx.x] = s1 * __expf(m1 - mn) + s2 * __expf(m2 - mn);
            rm[threadIdx.x] = mn;
        }
        __syncthreads();
    }
    if (threadIdx.x == 0) {
        int t = tg[row];
        if (t != 0) {
            float lse = rm[0] + logf(rs[0]);
            atomicAdd(num, lse - logits[(size_t)row * VOC + t]);
            atomicAdd(den, 1.0f);
        }
    }
}

__global__ void final_loss_k(const float* num, const float* den, float* out) {
    out[0] = *num / fmaxf(*den, 1.0f);
}

// ---------------------------------------------------------------------------
extern "C" void kernel_launch(void* const* d_in, const int* in_sizes, int n_in,
                              void* d_out, int out_size) {
    const int*   idx     = (const int*)d_in[0];
    const int*   targets = (const int*)d_in[1];
    const float* wte     = (const float*)d_in[2];
    const float* wpe     = (const float*)d_in[3];
    const float* ln1_g   = (const float*)d_in[4];
    const float* ln1_b   = (const float*)d_in[5];
    const float* attn_w  = (const float*)d_in[6];
    const float* attn_b  = (const float*)d_in[7];
    const float* proj_w  = (const float*)d_in[8];
    const float* proj_b  = (const float*)d_in[9];
    const float* ln2_g   = (const float*)d_in[10];
    const float* ln2_b   = (const float*)d_in[11];
    const float* fc_w    = (const float*)d_in[12];
    const float* fc_b    = (const float*)d_in[13];
    const float* fc2_w   = (const float*)d_in[14];
    const float* fc2_b   = (const float*)d_in[15];
    const float* lnf_g   = (const float*)d_in[16];
    const float* lnf_b   = (const float*)d_in[17];
    float* out = (float*)d_out;

    float *x, *h, *pnum, *pden;
    __half *qkv_h, *h_h, *y_h, *m_h, *wt_h, *wte_h;
    cudaGetSymbolAddress((void**)&x, g_x);
    cudaGetSymbolAddress((void**)&h, g_hf);
    cudaGetSymbolAddress((void**)&qkv_h, g_qkv_h);
    cudaGetSymbolAddress((void**)&h_h, g_h_h);
    cudaGetSymbolAddress((void**)&y_h, g_y_h);
    cudaGetSymbolAddress((void**)&m_h, g_m_h);
    cudaGetSymbolAddress((void**)&wt_h, g_wt_h);
    cudaGetSymbolAddress((void**)&wte_h, g_wte_h);
    cudaGetSymbolAddress((void**)&pnum, g_num);
    cudaGetSymbolAddress((void**)&pden, g_den);

    const size_t LOGN = (size_t)BT * VOC;
    float* out_loss = out + LOGN;
    float* out_x    = out + LOGN + 1;  // 4B-aligned only: scalar access

    cudaFuncSetAttribute(hgemm_k<0>, cudaFuncAttributeMaxDynamicSharedMemorySize, HSMEM);
    cudaFuncSetAttribute(hgemm_k<1>, cudaFuncAttributeMaxDynamicSharedMemorySize, HSMEM);
    cudaFuncSetAttribute(hgemm_k<2>, cudaFuncAttributeMaxDynamicSharedMemorySize, HSMEM);
    cudaFuncSetAttribute(hgemm_k<3>, cudaFuncAttributeMaxDynamicSharedMemorySize, HSMEM);
    cudaFuncSetAttribute(hgemm_k<4>, cudaFuncAttributeMaxDynamicSharedMemorySize, HSMEM);
    cudaFuncSetAttribute(flash_k, cudaFuncAttributeMaxDynamicSharedMemorySize, FSMEM);

    dim3 tblk(32, 8);

    // ---- weight preprocessing (batched over layers) ----
    conv_k<<<(VOC * CH / 4 + 255) / 256, 256>>>((const float4*)wte, wte_h, VOC * CH / 4);
    tconv_k<<<dim3(2304 / 32, 768 / 32, NLAY), tblk>>>(
        attn_w, wt_h + W_ATTN_OFF, 768, 2304, (size_t)W_ATTN_SZ, (size_t)W_ATTN_SZ);
    tconv_k<<<dim3(768 / 32, 768 / 32, NLAY), tblk>>>(
        proj_w, wt_h + W_PROJ_OFF, 768, 768, (size_t)W_PROJ_SZ, (size_t)W_PROJ_SZ);
    tconv_k<<<dim3(3072 / 32, 768 / 32, NLAY), tblk>>>(
        fc_w, wt_h + W_FC_OFF, 768, 3072, (size_t)W_FC_SZ, (size_t)W_FC_SZ);
    tconv_k<<<dim3(768 / 32, 3072 / 32, NLAY), tblk>>>(
        fc2_w, wt_h + W_FC2_OFF, 3072, 768, (size_t)W_FC2_SZ, (size_t)W_FC2_SZ);

    embed_k<<<BT, 256>>>(idx, wte, wpe, x);

    for (int l = 0; l < NLAY; l++) {
        const __half* wa = wt_h + W_ATTN_OFF + (size_t)l * W_ATTN_SZ;
        const __half* wp = wt_h + W_PROJ_OFF + (size_t)l * W_PROJ_SZ;
        const __half* wf = wt_h + W_FC_OFF + (size_t)l * W_FC_SZ;
        const __half* w2 = wt_h + W_FC2_OFF + (size_t)l * W_FC2_SZ;

        ln_k<0><<<BT / 8, 256>>>(x, ln1_g + l * CH, ln1_b + l * CH, nullptr, h_h);
        hgemm_k<4><<<dim3(2304 / 128, BT / 128), 256, HSMEM>>>(
            h_h, wa, attn_b + (size_t)l * 3 * CH, nullptr, nullptr, qkv_h, BT, 3 * CH, CH);
        flash_k<<<dim3(TSEQ / 128, NH, 4), 256, FSMEM>>>(qkv_h, y_h);
        hgemm_k<2><<<dim3(CH / 128, BT / 128), 256, HSMEM>>>(
            y_h, wp, proj_b + (size_t)l * CH, x, x, nullptr, BT, CH, CH);
        ln_k<0><<<BT / 8, 256>>>(x, ln2_g + l * CH, ln2_b + l * CH, nullptr, h_h);
        hgemm_k<1><<<dim3(4 * CH / 128, BT / 128), 256, HSMEM>>>(
            h_h, wf, fc_b + (size_t)l * 4 * CH, nullptr, nullptr, m_h, BT, 4 * CH, CH);
        hgemm_k<2><<<dim3(CH / 128, BT / 128), 256, HSMEM>>>(
            m_h, w2, fc2_b + (size_t)l * CH, x, x, nullptr, BT, CH, 4 * CH);
    }

    ln_k<1><<<BT / 8, 256>>>(x, lnf_g, lnf_b, h, h_h);
    copy_k<<<(BT * CH + 255) / 256, 256>>>(h, out_x, BT * CH);
    hgemm_k<3><<<dim3(VOC / 128, BT / 128), 256, HSMEM>>>(
        h_h, wte_h, nullptr, nullptr, out, nullptr, BT, VOC, CH);
    zero_loss_k<<<1, 1>>>(pnum, pden);
    loss_k<<<BT, 256>>>(out, targets, pnum, pden);
    final_loss_k<<<1, 1>>>(pnum, pden, out_loss);
}

// round 17
// speedup vs baseline: 1.2012x; 1.0040x over previous
#include <cuda_runtime.h>
#include <cuda_bf16.h>
#include <cuda_fp16.h>
#include <math.h>
#include <stdint.h>

// ---------------------------------------------------------------------------
// GPT-2 small forward: L=6, C=768, H=12, D=64, B=4, T=1024, V=32000
// Output layout: logits [4096*32000] | loss [1] | x_final [4096*768]
// Round 17: flash exp2f (folded scale, 1 MUFU/score), final-LN writes out_x
// directly (copy_k removed).  Otherwise identical to round 16.
// ---------------------------------------------------------------------------

#define BT   4096
#define CH   768
#define NH   12
#define DH   64
#define TSEQ 1024
#define VOC  32000
#define NLAY 6

#define W_ATTN_OFF 0
#define W_ATTN_SZ  (2304 * 768)
#define W_PROJ_OFF (W_ATTN_OFF + 6 * W_ATTN_SZ)
#define W_PROJ_SZ  (768 * 768)
#define W_FC_OFF   (W_PROJ_OFF + 6 * W_PROJ_SZ)
#define W_FC_SZ    (3072 * 768)
#define W_FC2_OFF  (W_FC_OFF + 6 * W_FC_SZ)
#define W_FC2_SZ   (768 * 3072)
#define W_TOTAL    (W_FC2_OFF + 6 * W_FC2_SZ)

// log2(e) * 0.125  (attention scale folded into exp2)
#define FSC 0.18033688011112042f

// Scratch (device globals: no allocation allowed)
__device__ float g_x[BT * CH];
__device__ __half g_qkv_h[BT * 3 * CH];
__device__ __half g_h_h[BT * CH];
__device__ __half g_y_h[BT * CH];
__device__ __half g_m_h[BT * 4 * CH];
__device__ __half g_wt_h[W_TOTAL];
__device__ __half g_wte_h[VOC * CH];
__device__ float g_num;
__device__ float g_den;

// ---------------------------------------------------------------------------
__global__ void conv_k(const float4* __restrict__ src, __half* __restrict__ dst, int n4) {
    int i = blockIdx.x * 256 + threadIdx.x;
    if (i < n4) {
        float4 v = src[i];
        *(__half2*)&dst[i * 4] = __floats2half2_rn(v.x, v.y);
        *(__half2*)&dst[i * 4 + 2] = __floats2half2_rn(v.z, v.w);
    }
}

// batched transpose + convert: W[l][K,N] fp32 -> T[l][N,K] fp16, blockIdx.z = layer
__global__ void tconv_k(const float* __restrict__ W, __half* __restrict__ T,
                        int K, int N, size_t wstride, size_t tstride) {
    __shared__ float s[32][33];
    int n0 = blockIdx.x * 32, k0 = blockIdx.y * 32;
    const float* Wl = W + (size_t)blockIdx.z * wstride;
    __half* Tl = T + (size_t)blockIdx.z * tstride;
    int tx = threadIdx.x, ty = threadIdx.y;
#pragma unroll
    for (int i = 0; i < 4; i++)
        s[ty + i * 8][tx] = Wl[(size_t)(k0 + ty + i * 8) * N + n0 + tx];
    __syncthreads();
#pragma unroll
    for (int i = 0; i < 4; i++)
        Tl[(size_t)(n0 + ty + i * 8) * K + k0 + tx] = __float2half(s[tx][ty + i * 8]);
}

// ---------------------------------------------------------------------------
__global__ void embed_k(const int* __restrict__ idx, const float* __restrict__ wte,
                        const float* __restrict__ wpe, float* __restrict__ x) {
    int row = blockIdx.x;
    int t = row & (TSEQ - 1);
    int tok = idx[row];
    const float* a = wte + (size_t)tok * CH;
    const float* b = wpe + (size_t)t * CH;
    float* o = x + (size_t)row * CH;
    for (int c = threadIdx.x; c < CH; c += blockDim.x) o[c] = a[c] + b[c];
}

// LayerNorm: one WARP per row, float4 loads, shfl reductions, no block sync.
// WF32=1: also write fp32 output with SCALAR stores (out_x is only 4B-aligned).
template <int WF32>
__global__ void ln_k(const float* __restrict__ x, const float* __restrict__ g,
                     const float* __restrict__ b, float* __restrict__ o,
                     __half* __restrict__ oh) {
    int row = blockIdx.x * 8 + (threadIdx.x >> 5);
    int lane = threadIdx.x & 31;
    const float4* xr = (const float4*)(x + (size_t)row * CH);
    float4 v[6];
    float s = 0.f, s2 = 0.f;
#pragma unroll
    for (int i = 0; i < 6; i++) {
        v[i] = xr[lane + i * 32];
        s  += v[i].x + v[i].y + v[i].z + v[i].w;
        s2 += v[i].x * v[i].x + v[i].y * v[i].y + v[i].z * v[i].z + v[i].w * v[i].w;
    }
#pragma unroll
    for (int off = 16; off > 0; off >>= 1) {
        s  += __shfl_xor_sync(0xffffffffu, s, off);
        s2 += __shfl_xor_sync(0xffffffffu, s2, off);
    }
    float mean = s * (1.0f / CH);
    float var  = s2 * (1.0f / CH) - mean * mean;
    float rstd = rsqrtf(var + 1e-5f);
    const float4* gg = (const float4*)g;
    const float4* bb = (const float4*)b;
#pragma unroll
    for (int i = 0; i < 6; i++) {
        int c4 = lane + i * 32;
        float4 gv = gg[c4], bv = bb[c4];
        float o0 = (v[i].x - mean) * rstd * gv.x + bv.x;
        float o1 = (v[i].y - mean) * rstd * gv.y + bv.y;
        float o2 = (v[i].z - mean) * rstd * gv.z + bv.z;
        float o3 = (v[i].w - mean) * rstd * gv.w + bv.w;
        size_t oo = (size_t)row * CH + c4 * 4;
        if (WF32) {  // scalar stores: o may be 4B-aligned only
            o[oo] = o0; o[oo + 1] = o1; o[oo + 2] = o2; o[oo + 3] = o3;
        }
        *(__half2*)&oh[oo] = __floats2half2_rn(o0, o1);
        *(__half2*)&oh[oo + 2] = __floats2half2_rn(o2, o3);
    }
}

// ---------------------------------------------------------------------------
// primitives
__device__ __forceinline__ void ldmx4(unsigned addr, unsigned r[4]) {
    asm volatile("ldmatrix.sync.aligned.m8n8.x4.shared.b16 {%0,%1,%2,%3}, [%4];"
                 : "=r"(r[0]), "=r"(r[1]), "=r"(r[2]), "=r"(r[3]) : "r"(addr));
}
__device__ __forceinline__ void ldmx4t(unsigned addr, unsigned r[4]) {
    asm volatile("ldmatrix.sync.aligned.m8n8.x4.trans.shared.b16 {%0,%1,%2,%3}, [%4];"
                 : "=r"(r[0]), "=r"(r[1]), "=r"(r[2]), "=r"(r[3]) : "r"(addr));
}
__device__ __forceinline__ void mma16816h(float d[4], const unsigned a[4],
                                          unsigned b0, unsigned b1) {
    asm volatile("mma.sync.aligned.m16n8k16.row.col.f32.f16.f16.f32 "
                 "{%0,%1,%2,%3},{%4,%5,%6,%7},{%8,%9},{%0,%1,%2,%3};"
                 : "+f"(d[0]), "+f"(d[1]), "+f"(d[2]), "+f"(d[3])
                 : "r"(a[0]), "r"(a[1]), "r"(a[2]), "r"(a[3]), "r"(b0), "r"(b1));
}
__device__ __forceinline__ void cp16(unsigned sa, const void* gm) {
    asm volatile("cp.async.cg.shared.global [%0], [%1], 16;" :: "r"(sa), "l"(gm));
}
__device__ __forceinline__ void cp_commit() { asm volatile("cp.async.commit_group;"); }
template <int N>
__device__ __forceinline__ void cp_wait() {
    asm volatile("cp.async.wait_group %0;" :: "n"(N));
}

#define SPITCH 40
#define ARR    (128 * SPITCH)
#define STGB   (2 * ARR * 2)
#define HSMEM  (2 * STGB)

// ---------------------------------------------------------------------------
// fp16 NT GEMM: D[M,N] = A[M,K] @ (B[N,K])^T, fp32 accum.
// MODE 0: +bias->fp32.  MODE 1: +bias,GELU->fp16.  MODE 2: +bias+res->fp32.
// MODE 3: plain->fp32.  MODE 4: +bias->fp16.
template <int MODE>
__global__ __launch_bounds__(256, 2)
void hgemm_k(const __half* __restrict__ A, const __half* __restrict__ B,
             const float* __restrict__ bias, const float* __restrict__ res,
             float* __restrict__ C, __half* __restrict__ O,
             int M, int N, int K) {
    extern __shared__ __align__(16) __half smbuf[];
    int tid = threadIdx.x, lane = tid & 31, wid = tid >> 5;
    int wm = wid >> 2, wn = wid & 3;
    int row0 = blockIdx.y * 128, col0 = blockIdx.x * 128;

    int r0 = tid >> 2, sg = (tid & 3) * 8;
    size_t aoff0 = (size_t)(row0 + r0) * K + sg;
    size_t aoff1 = aoff0 + (size_t)64 * K;
    size_t boff0 = (size_t)(col0 + r0) * K + sg;
    size_t boff1 = boff0 + (size_t)64 * K;
    int sm0 = r0 * SPITCH + sg, sm1 = sm0 + 64 * SPITCH;

    unsigned smbase = (unsigned)__cvta_generic_to_shared(smbuf);
    unsigned dA0 = smbase + sm0 * 2,         dA1 = smbase + sm1 * 2;
    unsigned dB0 = smbase + (ARR + sm0) * 2, dB1 = smbase + (ARR + sm1) * 2;

    int lr  = (lane & 7) + ((lane >> 3) & 1) * 8;
    int lcb = (lane >> 4) * 16;
    unsigned adA[4], adB[2];
#pragma unroll
    for (int i = 0; i < 4; i++) {
        int rr = wm * 64 + i * 16 + lr;
        adA[i] = smbase + (unsigned)(rr * SPITCH) * 2 + lcb;
    }
#pragma unroll
    for (int p = 0; p < 2; p++) {
        int rr = wn * 32 + p * 16 + lr;
        adB[p] = smbase + (unsigned)(ARR + rr * SPITCH) * 2 + lcb;
    }

    float acc[4][4][4];
#pragma unroll
    for (int i = 0; i < 4; i++)
#pragma unroll
        for (int j = 0; j < 4; j++)
#pragma unroll
            for (int q = 0; q < 4; q++) acc[i][j][q] = 0.f;

    int nC = K >> 5;
    cp16(dA0, A + aoff0); cp16(dA1, A + aoff1);
    cp16(dB0, B + boff0); cp16(dB1, B + boff1);
    cp_commit();

    for (int c = 0; c < nC; c++) {
        if (c + 1 < nC) {
            unsigned so = (unsigned)((c + 1) & 1) * STGB;
            size_t ko = (size_t)(c + 1) << 5;
            cp16(dA0 + so, A + aoff0 + ko); cp16(dA1 + so, A + aoff1 + ko);
            cp16(dB0 + so, B + boff0 + ko); cp16(dB1 + so, B + boff1 + ko);
            cp_commit();
            cp_wait<1>();
        } else {
            cp_wait<0>();
        }
        __syncthreads();

        unsigned so = (unsigned)(c & 1) * STGB;
#pragma unroll
        for (int s = 0; s < 2; s++) {
            unsigned ah[4][4], bh[2][4];
#pragma unroll
            for (int i = 0; i < 4; i++) ldmx4(adA[i] + so + s * 32, ah[i]);
#pragma unroll
            for (int p = 0; p < 2; p++) ldmx4(adB[p] + so + s * 32, bh[p]);
#pragma unroll
            for (int i = 0; i < 4; i++)
#pragma unroll
                for (int j = 0; j < 4; j++) {
                    int p = j >> 1, q = j & 1;
                    mma16816h(acc[i][j], ah[i], bh[p][q], bh[p][2 + q]);
                }
        }
        __syncthreads();
    }

    int g = lane >> 2, t2 = (lane & 3) * 2;
#pragma unroll
    for (int i = 0; i < 4; i++) {
        int rA = row0 + wm * 64 + i * 16 + g;
#pragma unroll
        for (int j = 0; j < 4; j++) {
            int cA = col0 + wn * 32 + j * 8 + t2;
            float v0 = acc[i][j][0], v1 = acc[i][j][1];
            float w0 = acc[i][j][2], w1 = acc[i][j][3];
            if (MODE != 3) {
                float b0 = bias[cA], b1 = bias[cA + 1];
                v0 += b0; v1 += b1; w0 += b0; w1 += b1;
            }
            if (MODE == 1) {
                v0 = 0.5f * v0 * (1.0f + erff(v0 * 0.70710678118654752440f));
                v1 = 0.5f * v1 * (1.0f + erff(v1 * 0.70710678118654752440f));
                w0 = 0.5f * w0 * (1.0f + erff(w0 * 0.70710678118654752440f));
                w1 = 0.5f * w1 * (1.0f + erff(w1 * 0.70710678118654752440f));
            }
            if (MODE == 1 || MODE == 4) {
                *(__half2*)&O[(size_t)rA * N + cA] = __floats2half2_rn(v0, v1);
                *(__half2*)&O[(size_t)(rA + 8) * N + cA] = __floats2half2_rn(w0, w1);
            } else {
                if (MODE == 2) {
                    float2 q0 = *(const float2*)&res[(size_t)rA * N + cA];
                    float2 q1 = *(const float2*)&res[(size_t)(rA + 8) * N + cA];
                    v0 += q0.x; v1 += q0.y; w0 += q1.x; w1 += q1.y;
                }
                *(float2*)&C[(size_t)rA * N + cA] = make_float2(v0, v1);
                *(float2*)&C[(size_t)(rA + 8) * N + cA] = make_float2(w0, w1);
            }
        }
    }
}

// ---------------------------------------------------------------------------
// Flash attention: q-tile 128, s-tile 64, fp16 mma, online softmax (base-2,
// scale folded: exp(x*0.125) == exp2(x*FSC)).
#define FKP   72
#define FQB   (128 * FKP * 2)
#define FKVST (64 * FKP * 2)
#define FSTG  (2 * FKVST)
#define FSMEM (FQB + 2 * FSTG)

__global__ __launch_bounds__(256)
void flash_k(const __half* __restrict__ qkv, __half* __restrict__ y) {
    extern __shared__ __align__(16) __half fsm[];
    int tid = threadIdx.x, lane = tid & 31, wid = tid >> 5;
    int qt = gridDim.x - 1 - blockIdx.x;   // heavy tiles first
    int h = blockIdx.y, b = blockIdx.z;
    int q0 = qt * 128;
    const __half* base = qkv + (size_t)b * TSEQ * (3 * CH);
    unsigned Qb = (unsigned)__cvta_generic_to_shared(fsm);
    unsigned KVb = Qb + FQB;

#pragma unroll
    for (int i = 0; i < 4; i++) {
        int idx = tid + i * 256;
        int row = idx >> 3, seg = idx & 7;
        cp16(Qb + row * 144 + seg * 16,
             base + (size_t)(q0 + row) * (3 * CH) + h * DH + seg * 8);
    }
#pragma unroll
    for (int i = 0; i < 2; i++) {
        int idx = tid + i * 256;
        int row = idx >> 3, seg = idx & 7;
        cp16(KVb + row * 144 + seg * 16,
             base + (size_t)row * (3 * CH) + CH + h * DH + seg * 8);
        cp16(KVb + FKVST + row * 144 + seg * 16,
             base + (size_t)row * (3 * CH) + 2 * CH + h * DH + seg * 8);
    }
    cp_commit();

    int lr  = (lane & 7) + ((lane >> 3) & 1) * 8;
    int lcb = (lane >> 4) * 16;
    unsigned qad[4];
#pragma unroll
    for (int kk = 0; kk < 4; kk++)
        qad[kk] = Qb + (unsigned)((wid * 16 + lr) * 144) + kk * 32 + lcb;

    unsigned Qf[4][4];
    float Oa[8][4];
#pragma unroll
    for (int j = 0; j < 8; j++)
#pragma unroll
        for (int q = 0; q < 4; q++) Oa[j][q] = 0.f;
    // m0,m1 track max in exp2-domain (score * FSC)
    float m0 = -1e30f, m1 = -1e30f, l0 = 0.f, l1 = 0.f;

    int nT = 2 * (qt + 1);
    for (int t = 0; t < nT; t++) {
        if (t + 1 < nT) {
            unsigned kb = KVb + (unsigned)((t + 1) & 1) * FSTG;
            int s0n = (t + 1) * 64;
#pragma unroll
            for (int i = 0; i < 2; i++) {
                int idx = tid + i * 256;
                int row = idx >> 3, seg = idx & 7;
                cp16(kb + row * 144 + seg * 16,
                     base + (size_t)(s0n + row) * (3 * CH) + CH + h * DH + seg * 8);
                cp16(kb + FKVST + row * 144 + seg * 16,
                     base + (size_t)(s0n + row) * (3 * CH) + 2 * CH + h * DH + seg * 8);
            }
            cp_commit();
            cp_wait<1>();
        } else {
            cp_wait<0>();
        }
        __syncthreads();
        if (t == 0) {
#pragma unroll
            for (int kk = 0; kk < 4; kk++) ldmx4(qad[kk], Qf[kk]);
        }
        unsigned kb = KVb + (unsigned)(t & 1) * FSTG;

        float S[8][4];
#pragma unroll
        for (int j = 0; j < 8; j++)
#pragma unroll
            for (int q = 0; q < 4; q++) S[j][q] = 0.f;
#pragma unroll
        for (int kk = 0; kk < 4; kk++) {
            unsigned kf[4][4];
#pragma unroll
            for (int p = 0; p < 4; p++)
                ldmx4(kb + (unsigned)((p * 16 + lr) * 144) + kk * 32 + lcb, kf[p]);
#pragma unroll
            for (int p = 0; p < 4; p++)
#pragma unroll
                for (int qn = 0; qn < 2; qn++)
                    mma16816h(S[p * 2 + qn], Qf[kk], kf[p][qn], kf[p][2 + qn]);
        }

        int s0 = t * 64;
        int rg = q0 + wid * 16 + (lane >> 2);
        if (s0 + 63 > q0 + wid * 16) {
#pragma unroll
            for (int j = 0; j < 8; j++) {
                int sc = s0 + j * 8 + (lane & 3) * 2;
                if (sc > rg)     S[j][0] = -1e30f;
                if (sc + 1 > rg) S[j][1] = -1e30f;
                if (sc > rg + 8)     S[j][2] = -1e30f;
                if (sc + 1 > rg + 8) S[j][3] = -1e30f;
            }
        }
        float mx0 = -1e30f, mx1 = -1e30f;
#pragma unroll
        for (int j = 0; j < 8; j++) {
            mx0 = fmaxf(mx0, fmaxf(S[j][0], S[j][1]));
            mx1 = fmaxf(mx1, fmaxf(S[j][2], S[j][3]));
        }
        mx0 = fmaxf(mx0, __shfl_xor_sync(0xffffffffu, mx0, 1));
        mx0 = fmaxf(mx0, __shfl_xor_sync(0xffffffffu, mx0, 2));
        mx1 = fmaxf(mx1, __shfl_xor_sync(0xffffffffu, mx1, 1));
        mx1 = fmaxf(mx1, __shfl_xor_sync(0xffffffffu, mx1, 2));
        mx0 *= FSC; mx1 *= FSC;   // exp2 domain
        float mn0 = fmaxf(m0, mx0), mn1 = fmaxf(m1, mx1);
        float a0 = exp2f(m0 - mn0), a1 = exp2f(m1 - mn1);
        m0 = mn0; m1 = mn1;
        float rs0 = 0.f, rs1 = 0.f;
        __half2 P[8][2];
#pragma unroll
        for (int j = 0; j < 8; j++) {
            float p0 = exp2f(fmaf(S[j][0], FSC, -m0));
            float p1 = exp2f(fmaf(S[j][1], FSC, -m0));
            float p2 = exp2f(fmaf(S[j][2], FSC, -m1));
            float p3 = exp2f(fmaf(S[j][3], FSC, -m1));
            rs0 += p0 + p1; rs1 += p2 + p3;
            P[j][0] = __floats2half2_rn(p0, p1);
            P[j][1] = __floats2half2_rn(p2, p3);
        }
        l0 = l0 * a0 + rs0; l1 = l1 * a1 + rs1;
#pragma unroll
        for (int j = 0; j < 8; j++) {
            Oa[j][0] *= a0; Oa[j][1] *= a0; Oa[j][2] *= a1; Oa[j][3] *= a1;
        }
        unsigned vb = kb + FKVST;
#pragma unroll
        for (int kt = 0; kt < 4; kt++) {
            unsigned vf[4][4];
#pragma unroll
            for (int dg = 0; dg < 4; dg++)
                ldmx4t(vb + (unsigned)((kt * 16 + lr) * 144) + dg * 32 + lcb, vf[dg]);
            unsigned pa[4];
            pa[0] = *(unsigned*)&P[2 * kt][0];
            pa[1] = *(unsigned*)&P[2 * kt][1];
            pa[2] = *(unsigned*)&P[2 * kt + 1][0];
            pa[3] = *(unsigned*)&P[2 * kt + 1][1];
#pragma unroll
            for (int dg = 0; dg < 4; dg++) {
                mma16816h(Oa[dg * 2 + 0], pa, vf[dg][0], vf[dg][1]);
                mma16816h(Oa[dg * 2 + 1], pa, vf[dg][2], vf[dg][3]);
            }
        }
        __syncthreads();
    }

    l0 += __shfl_xor_sync(0xffffffffu, l0, 1);
    l0 += __shfl_xor_sync(0xffffffffu, l0, 2);
    l1 += __shfl_xor_sync(0xffffffffu, l1, 1);
    l1 += __shfl_xor_sync(0xffffffffu, l1, 2);
    float inv0 = 1.0f / l0, inv1 = 1.0f / l1;
    int g = lane >> 2, t2 = (lane & 3) * 2;
    int rowg = q0 + wid * 16 + g;
#pragma unroll
    for (int j = 0; j < 8; j++) {
        int d = h * DH + j * 8 + t2;
        *(__half2*)&y[(size_t)(b * TSEQ + rowg) * CH + d] =
            __floats2half2_rn(Oa[j][0] * inv0, Oa[j][1] * inv0);
        *(__half2*)&y[(size_t)(b * TSEQ + rowg + 8) * CH + d] =
            __floats2half2_rn(Oa[j][2] * inv1, Oa[j][3] * inv1);
    }
}

// ---------------------------------------------------------------------------
__global__ void zero_loss_k(float* num, float* den) { *num = 0.f; *den = 0.f; }

// single-pass online log-sum-exp NLL (float4 reads)
__global__ void loss_k(const float* __restrict__ logits, const int* __restrict__ tg,
                       float* num, float* den) {
    __shared__ float rm[256], rs[256];
    int row = blockIdx.x;
    const float4* lr4 = (const float4*)(logits + (size_t)row * VOC);
    float m = -3.0e38f, s = 0.f;
    for (int j = threadIdx.x; j < VOC / 4; j += 256) {
        float4 v = lr4[j];
        float vm = fmaxf(fmaxf(v.x, v.y), fmaxf(v.z, v.w));
        if (vm > m) { s = s * __expf(m - vm); m = vm; }
        s += __expf(v.x - m) + __expf(v.y - m) + __expf(v.z - m) + __expf(v.w - m);
    }
    rm[threadIdx.x] = m; rs[threadIdx.x] = s;
    __syncthreads();
    for (int off = 128; off > 0; off >>= 1) {
        if (threadIdx.x < off) {
            float m2 = rm[threadIdx.x + off], s2 = rs[threadIdx.x + off];
            float m1 = rm[threadIdx.x], s1 = rs[threadIdx.x];
            float mn = fmaxf(m1, m2);
            rs[threadIdx.x] = s1 * __expf(m1 - mn) + s2 * __expf(m2 - mn);
            rm[threadIdx.x] = mn;
        }
        __syncthreads();
    }
    if (threadIdx.x == 0) {
        int t = tg[row];
        if (t != 0) {
            float lse = rm[0] + logf(rs[0]);
            atomicAdd(num, lse - logits[(size_t)row * VOC + t]);
            atomicAdd(den, 1.0f);
        }
    }
}

__global__ void final_loss_k(const float* num, const float* den, float* out) {
    out[0] = *num / fmaxf(*den, 1.0f);
}

// ---------------------------------------------------------------------------
extern "C" void kernel_launch(void* const* d_in, const int* in_sizes, int n_in,
                              void* d_out, int out_size) {
    const int*   idx     = (const int*)d_in[0];
    const int*   targets = (const int*)d_in[1];
    const float* wte     = (const float*)d_in[2];
    const float* wpe     = (const float*)d_in[3];
    const float* ln1_g   = (const float*)d_in[4];
    const float* ln1_b   = (const float*)d_in[5];
    const float* attn_w  = (const float*)d_in[6];
    const float* attn_b  = (const float*)d_in[7];
    const float* proj_w  = (const float*)d_in[8];
    const float* proj_b  = (const float*)d_in[9];
    const float* ln2_g   = (const float*)d_in[10];
    const float* ln2_b   = (const float*)d_in[11];
    const float* fc_w    = (const float*)d_in[12];
    const float* fc_b    = (const float*)d_in[13];
    const float* fc2_w   = (const float*)d_in[14];
    const float* fc2_b   = (const float*)d_in[15];
    const float* lnf_g   = (const float*)d_in[16];
    const float* lnf_b   = (const float*)d_in[17];
    float* out = (float*)d_out;

    float *x, *pnum, *pden;
    __half *qkv_h, *h_h, *y_h, *m_h, *wt_h, *wte_h;
    cudaGetSymbolAddress((void**)&x, g_x);
    cudaGetSymbolAddress((void**)&qkv_h, g_qkv_h);
    cudaGetSymbolAddress((void**)&h_h, g_h_h);
    cudaGetSymbolAddress((void**)&y_h, g_y_h);
    cudaGetSymbolAddress((void**)&m_h, g_m_h);
    cudaGetSymbolAddress((void**)&wt_h, g_wt_h);
    cudaGetSymbolAddress((void**)&wte_h, g_wte_h);
    cudaGetSymbolAddress((void**)&pnum, g_num);
    cudaGetSymbolAddress((void**)&pden, g_den);

    const size_t LOGN = (size_t)BT * VOC;
    float* out_loss = out + LOGN;
    float* out_x    = out + LOGN + 1;  // 4B-aligned only: scalar access

    cudaFuncSetAttribute(hgemm_k<0>, cudaFuncAttributeMaxDynamicSharedMemorySize, HSMEM);
    cudaFuncSetAttribute(hgemm_k<1>, cudaFuncAttributeMaxDynamicSharedMemorySize, HSMEM);
    cudaFuncSetAttribute(hgemm_k<2>, cudaFuncAttributeMaxDynamicSharedMemorySize, HSMEM);
    cudaFuncSetAttribute(hgemm_k<3>, cudaFuncAttributeMaxDynamicSharedMemorySize, HSMEM);
    cudaFuncSetAttribute(hgemm_k<4>, cudaFuncAttributeMaxDynamicSharedMemorySize, HSMEM);
    cudaFuncSetAttribute(flash_k, cudaFuncAttributeMaxDynamicSharedMemorySize, FSMEM);

    dim3 tblk(32, 8);

    // ---- weight preprocessing (batched over layers) ----
    conv_k<<<(VOC * CH / 4 + 255) / 256, 256>>>((const float4*)wte, wte_h, VOC * CH / 4);
    tconv_k<<<dim3(2304 / 32, 768 / 32, NLAY), tblk>>>(
        attn_w, wt_h + W_ATTN_OFF, 768, 2304, (size_t)W_ATTN_SZ, (size_t)W_ATTN_SZ);
    tconv_k<<<dim3(768 / 32, 768 / 32, NLAY), tblk>>>(
        proj_w, wt_h + W_PROJ_OFF, 768, 768, (size_t)W_PROJ_SZ, (size_t)W_PROJ_SZ);
    tconv_k<<<dim3(3072 / 32, 768 / 32, NLAY), tblk>>>(
        fc_w, wt_h + W_FC_OFF, 768, 3072, (size_t)W_FC_SZ, (size_t)W_FC_SZ);
    tconv_k<<<dim3(768 / 32, 3072 / 32, NLAY), tblk>>>(
        fc2_w, wt_h + W_FC2_OFF, 3072, 768, (size_t)W_FC2_SZ, (size_t)W_FC2_SZ);

    embed_k<<<BT, 256>>>(idx, wte, wpe, x);

    for (int l = 0; l < NLAY; l++) {
        const __half* wa = wt_h + W_ATTN_OFF + (size_t)l * W_ATTN_SZ;
        const __half* wp = wt_h + W_PROJ_OFF + (size_t)l * W_PROJ_SZ;
        const __half* wf = wt_h + W_FC_OFF + (size_t)l * W_FC_SZ;
        const __half* w2 = wt_h + W_FC2_OFF + (size_t)l * W_FC2_SZ;

        ln_k<0><<<BT / 8, 256>>>(x, ln1_g + l * CH, ln1_b + l * CH, nullptr, h_h);
        hgemm_k<4><<<dim3(2304 / 128, BT / 128), 256, HSMEM>>>(
            h_h, wa, attn_b + (size_t)l * 3 * CH, nullptr, nullptr, qkv_h, BT, 3 * CH, CH);
        flash_k<<<dim3(TSEQ / 128, NH, 4), 256, FSMEM>>>(qkv_h, y_h);
        hgemm_k<2><<<dim3(CH / 128, BT / 128), 256, HSMEM>>>(
            y_h, wp, proj_b + (size_t)l * CH, x, x, nullptr, BT, CH, CH);
        ln_k<0><<<BT / 8, 256>>>(x, ln2_g + l * CH, ln2_b + l * CH, nullptr, h_h);
        hgemm_k<1><<<dim3(4 * CH / 128, BT / 128), 256, HSMEM>>>(
            h_h, wf, fc_b + (size_t)l * 4 * CH, nullptr, nullptr, m_h, BT, 4 * CH, CH);
        hgemm_k<2><<<dim3(CH / 128, BT / 128), 256, HSMEM>>>(
            m_h, w2, fc2_b + (size_t)l * CH, x, x, nullptr, BT, CH, 4 * CH);
    }

    // final LN writes fp16 (for lm-head) and fp32 straight into out_x (scalar)
    ln_k<1><<<BT / 8, 256>>>(x, lnf_g, lnf_b, out_x, h_h);
    hgemm_k<3><<<dim3(VOC / 128, BT / 128), 256, HSMEM>>>(
        h_h, wte_h, nullptr, nullptr, out, nullptr, BT, VOC, CH);
    zero_loss_k<<<1, 1>>>(pnum, pden);
    loss_k<<<BT, 256>>>(out, targets, pnum, pden);
    final_loss_k<<<1, 1>>>(pnum, pden, out_loss);
}